// round 3
// baseline (speedup 1.0000x reference)
#include <cuda_runtime.h>
#include <math.h>

#define B_ 4
#define H_ 48
#define W_ 48
#define C_ 256
#define NH_ 8
#define D_ 32
#define N_ (H_*W_)          /* 2304 */
#define ROWS_ (B_*N_)       /* 9216 */
#define SCALE_ 0.17677669529663687f

// Scratch (device globals: no allocation allowed)
static __device__ float g_q[ROWS_*C_];
static __device__ float g_k[ROWS_*C_];
static __device__ float g_v[ROWS_*C_];
static __device__ float g_lepe[ROWS_*C_];
static __device__ float g_ctx[ROWS_*C_];

// ---------------------------------------------------------------------------
// Kernel 1: fused QKV GEMM (M=9216, K=256, Nout=256, z selects Q/K/V)
// 64x64 tile, 256 threads, 4x4 microtile. Epilogue: bias (+scale for K), RoPE
// for Q/K, write NHWC layout (row*256 + c).
// ---------------------------------------------------------------------------
__global__ __launch_bounds__(256) void qkv_kernel(
    const float* __restrict__ x,
    const float* __restrict__ Wq, const float* __restrict__ bq,
    const float* __restrict__ Wk, const float* __restrict__ bk,
    const float* __restrict__ Wv, const float* __restrict__ bv,
    const float* __restrict__ s_sin, const float* __restrict__ s_cos)
{
    __shared__ float As[16][68];
    __shared__ float Bs[16][68];

    const int mat = blockIdx.z;
    const float* Wm = (mat == 0) ? Wq : (mat == 1) ? Wk : Wv;
    const float* bm = (mat == 0) ? bq : (mat == 1) ? bk : bv;

    const int tid = threadIdx.x;
    const int tx = tid & 15, ty = tid >> 4;
    const int row0 = blockIdx.y * 64;
    const int col0 = blockIdx.x * 64;

    // load indices
    const int arow = tid >> 2;         // 0..63
    const int ak   = (tid & 3) * 4;    // 0,4,8,12
    const int bkr  = tid >> 4;         // 0..15
    const int bc   = (tid & 15) * 4;   // 0..60

    float acc[4][4] = {};

    for (int k0 = 0; k0 < C_; k0 += 16) {
        float4 av = *(const float4*)(x + (size_t)(row0 + arow) * C_ + k0 + ak);
        float4 bv4 = *(const float4*)(Wm + (size_t)(k0 + bkr) * C_ + col0 + bc);
        As[ak + 0][arow] = av.x;
        As[ak + 1][arow] = av.y;
        As[ak + 2][arow] = av.z;
        As[ak + 3][arow] = av.w;
        *(float4*)&Bs[bkr][bc] = bv4;
        __syncthreads();
#pragma unroll
        for (int kk = 0; kk < 16; kk++) {
            float4 a = *(const float4*)&As[kk][ty * 4];
            float4 b = *(const float4*)&Bs[kk][tx * 4];
            float aa[4] = {a.x, a.y, a.z, a.w};
            float bb[4] = {b.x, b.y, b.z, b.w};
#pragma unroll
            for (int i = 0; i < 4; i++)
#pragma unroll
                for (int j = 0; j < 4; j++)
                    acc[i][j] = fmaf(aa[i], bb[j], acc[i][j]);
        }
        __syncthreads();
    }

    // epilogue
    const int gcol = col0 + tx * 4;
    float bias[4];
#pragma unroll
    for (int j = 0; j < 4; j++) bias[j] = bm[gcol + j];

    float* dst = (mat == 0) ? g_q : (mat == 1) ? g_k : g_v;

#pragma unroll
    for (int i = 0; i < 4; i++) {
        int row = row0 + ty * 4 + i;
        int n = row % N_;
        float vals[4];
#pragma unroll
        for (int j = 0; j < 4; j++) {
            vals[j] = acc[i][j] + bias[j];
            if (mat == 1) vals[j] *= SCALE_;
        }
        if (mat < 2) {
            // RoPE on pairs (0,1) and (2,3); dd = channel % 32
#pragma unroll
            for (int p = 0; p < 4; p += 2) {
                int dd = (gcol + p) & (D_ - 1);
                float c0 = s_cos[n * D_ + dd];
                float s0 = s_sin[n * D_ + dd];
                float c1 = s_cos[n * D_ + dd + 1];
                float s1 = s_sin[n * D_ + dd + 1];
                float e = vals[p], o = vals[p + 1];
                vals[p]     = e * c0 - o * s0;
                vals[p + 1] = o * c1 + e * s1;
            }
        }
        *(float4*)&dst[(size_t)row * C_ + gcol] =
            make_float4(vals[0], vals[1], vals[2], vals[3]);
    }
}

// ---------------------------------------------------------------------------
// Kernel 2: depthwise 5x5 conv (LEPE) on v (NHWC), one block per pixel.
// ---------------------------------------------------------------------------
__global__ __launch_bounds__(256) void lepe_kernel(
    const float* __restrict__ dw_w, const float* __restrict__ dw_b)
{
    const int c = threadIdx.x;
    const int idx = blockIdx.x;              // b*H*W + y*W + x
    const int xp = idx % W_;
    const int t = idx / W_;
    const int y = t % H_;
    const int b = t / H_;

    float acc = dw_b[c];
#pragma unroll
    for (int dy = 0; dy < 5; dy++) {
        int yy = y + dy - 2;
        if (yy < 0 || yy >= H_) continue;
#pragma unroll
        for (int dx = 0; dx < 5; dx++) {
            int xx = xp + dx - 2;
            if (xx < 0 || xx >= W_) continue;
            acc = fmaf(g_v[(size_t)((b * H_ + yy) * W_ + xx) * C_ + c],
                       dw_w[(dy * 5 + dx) * C_ + c], acc);
        }
    }
    g_lepe[(size_t)idx * C_ + c] = acc;
}

// ---------------------------------------------------------------------------
// Kernel 3: flash attention per (b,h). BM=BN=128, d=32, 256 threads.
// Register-blocked 8x8 S-tile, mask add, online softmax, P via SMEM for PV.
// ---------------------------------------------------------------------------
#define BM_ 128
#define BN_ 128
#define QS_OFF 0
#define KS_OFF (32*132)
#define VS_OFF (2*32*132)
#define PS_OFF (2*32*132 + 128*36)
#define ATTN_SMEM_FLOATS (2*32*132 + 128*36 + 128*132)
#define ATTN_SMEM_BYTES (ATTN_SMEM_FLOATS * 4)

__global__ __launch_bounds__(256) void attn_kernel(const float* __restrict__ mask)
{
    extern __shared__ float sm[];
    float* qs = sm + QS_OFF;   // [32][132]  k-major q
    float* ks = sm + KS_OFF;   // [32][132]  k-major k
    float* vs = sm + VS_OFF;   // [128][36]
    float* Ps = sm + PS_OFF;   // [128][132]

    const int tid = threadIdx.x;
    const int tx = tid & 15, ty = tid >> 4;
    const int rb = blockIdx.x;            // 0..17
    const int bh = blockIdx.y;            // 0..31
    const int b = bh >> 3, h = bh & 7;
    const int row0 = rb * BM_;

    // load Q tile (transposed into qs[dd][row])
    const float* qbase = g_q + ((size_t)b * N_ + row0) * C_ + h * D_;
#pragma unroll
    for (int j = 0; j < 4; j++) {
        int e = tid * 16 + j * 4;
        int r = e >> 5, dd = e & 31;
        float4 t4 = *(const float4*)(qbase + (size_t)r * C_ + dd);
        qs[(dd + 0) * 132 + r] = t4.x;
        qs[(dd + 1) * 132 + r] = t4.y;
        qs[(dd + 2) * 132 + r] = t4.z;
        qs[(dd + 3) * 132 + r] = t4.w;
    }

    float m_i[8], l_i[8], o_i[8][2];
#pragma unroll
    for (int i = 0; i < 8; i++) {
        m_i[i] = -1e30f; l_i[i] = 0.f; o_i[i][0] = 0.f; o_i[i][1] = 0.f;
    }

    for (int mt = 0; mt < N_; mt += BN_) {
        __syncthreads();
        const float* kb = g_k + ((size_t)b * N_ + mt) * C_ + h * D_;
        const float* vb = g_v + ((size_t)b * N_ + mt) * C_ + h * D_;
#pragma unroll
        for (int j = 0; j < 4; j++) {
            int e = tid * 16 + j * 4;
            int r = e >> 5, dd = e & 31;
            float4 t4 = *(const float4*)(kb + (size_t)r * C_ + dd);
            ks[(dd + 0) * 132 + r] = t4.x;
            ks[(dd + 1) * 132 + r] = t4.y;
            ks[(dd + 2) * 132 + r] = t4.z;
            ks[(dd + 3) * 132 + r] = t4.w;
            float4 u4 = *(const float4*)(vb + (size_t)r * C_ + dd);
            *(float4*)&vs[r * 36 + dd] = u4;
        }
        __syncthreads();

        // GEMM1: S = q k^T  (8x8 per thread)
        float acc[8][8] = {};
#pragma unroll 8
        for (int kk = 0; kk < 32; kk++) {
            float4 a0 = *(const float4*)&qs[kk * 132 + ty * 8];
            float4 a1 = *(const float4*)&qs[kk * 132 + ty * 8 + 4];
            float4 b0 = *(const float4*)&ks[kk * 132 + tx * 8];
            float4 b1 = *(const float4*)&ks[kk * 132 + tx * 8 + 4];
            float aa[8] = {a0.x, a0.y, a0.z, a0.w, a1.x, a1.y, a1.z, a1.w};
            float bb[8] = {b0.x, b0.y, b0.z, b0.w, b1.x, b1.y, b1.z, b1.w};
#pragma unroll
            for (int i = 0; i < 8; i++)
#pragma unroll
                for (int j = 0; j < 8; j++)
                    acc[i][j] = fmaf(aa[i], bb[j], acc[i][j]);
        }

        // add mask
        const float* mb = mask + (size_t)h * N_ * N_
                        + (size_t)(row0 + ty * 8) * N_ + (mt + tx * 8);
#pragma unroll
        for (int i = 0; i < 8; i++) {
            float4 mv0 = *(const float4*)(mb + (size_t)i * N_);
            float4 mv1 = *(const float4*)(mb + (size_t)i * N_ + 4);
            acc[i][0] += mv0.x; acc[i][1] += mv0.y;
            acc[i][2] += mv0.z; acc[i][3] += mv0.w;
            acc[i][4] += mv1.x; acc[i][5] += mv1.y;
            acc[i][6] += mv1.z; acc[i][7] += mv1.w;
        }

        // online softmax per row; write P to SMEM
#pragma unroll
        for (int i = 0; i < 8; i++) {
            float mx = acc[i][0];
#pragma unroll
            for (int j = 1; j < 8; j++) mx = fmaxf(mx, acc[i][j]);
#pragma unroll
            for (int off = 8; off > 0; off >>= 1)
                mx = fmaxf(mx, __shfl_xor_sync(0xffffffffu, mx, off, 16));
            float mn = fmaxf(m_i[i], mx);
            float corr = __expf(m_i[i] - mn);
            m_i[i] = mn;
            float rs = 0.f;
#pragma unroll
            for (int j = 0; j < 8; j++) {
                acc[i][j] = __expf(acc[i][j] - mn);
                rs += acc[i][j];
            }
#pragma unroll
            for (int off = 8; off > 0; off >>= 1)
                rs += __shfl_xor_sync(0xffffffffu, rs, off, 16);
            l_i[i] = l_i[i] * corr + rs;
            o_i[i][0] *= corr;
            o_i[i][1] *= corr;
            *(float4*)&Ps[(ty * 8 + i) * 132 + tx * 8] =
                make_float4(acc[i][0], acc[i][1], acc[i][2], acc[i][3]);
            *(float4*)&Ps[(ty * 8 + i) * 132 + tx * 8 + 4] =
                make_float4(acc[i][4], acc[i][5], acc[i][6], acc[i][7]);
        }
        __syncthreads();

        // GEMM2: O += P @ V  (rows ty*8..+7, cols tx*2..+1)
#pragma unroll 4
        for (int mm = 0; mm < BN_; mm += 4) {
            float4 p[8];
#pragma unroll
            for (int i = 0; i < 8; i++)
                p[i] = *(const float4*)&Ps[(ty * 8 + i) * 132 + mm];
            float2 v0 = *(const float2*)&vs[(mm + 0) * 36 + tx * 2];
            float2 v1 = *(const float2*)&vs[(mm + 1) * 36 + tx * 2];
            float2 v2 = *(const float2*)&vs[(mm + 2) * 36 + tx * 2];
            float2 v3 = *(const float2*)&vs[(mm + 3) * 36 + tx * 2];
#pragma unroll
            for (int i = 0; i < 8; i++) {
                o_i[i][0] = fmaf(p[i].x, v0.x, o_i[i][0]);
                o_i[i][0] = fmaf(p[i].y, v1.x, o_i[i][0]);
                o_i[i][0] = fmaf(p[i].z, v2.x, o_i[i][0]);
                o_i[i][0] = fmaf(p[i].w, v3.x, o_i[i][0]);
                o_i[i][1] = fmaf(p[i].x, v0.y, o_i[i][1]);
                o_i[i][1] = fmaf(p[i].y, v1.y, o_i[i][1]);
                o_i[i][1] = fmaf(p[i].z, v2.y, o_i[i][1]);
                o_i[i][1] = fmaf(p[i].w, v3.y, o_i[i][1]);
            }
        }
    }

    // write ctx (NHWC)
#pragma unroll
    for (int i = 0; i < 8; i++) {
        float inv = 1.f / l_i[i];
        int r = row0 + ty * 8 + i;
        *(float2*)&g_ctx[((size_t)b * N_ + r) * C_ + h * D_ + tx * 2] =
            make_float2(o_i[i][0] * inv, o_i[i][1] * inv);
    }
}

// ---------------------------------------------------------------------------
// Kernel 4: out = (ctx + lepe) @ Wo + bo   (same GEMM shape as kernel 1)
// ---------------------------------------------------------------------------
__global__ __launch_bounds__(256) void out_kernel(
    const float* __restrict__ Wo, const float* __restrict__ bo,
    float* __restrict__ out)
{
    __shared__ float As[16][68];
    __shared__ float Bs[16][68];

    const int tid = threadIdx.x;
    const int tx = tid & 15, ty = tid >> 4;
    const int row0 = blockIdx.y * 64;
    const int col0 = blockIdx.x * 64;

    const int arow = tid >> 2;
    const int ak   = (tid & 3) * 4;
    const int bkr  = tid >> 4;
    const int bc   = (tid & 15) * 4;

    float acc[4][4] = {};

    for (int k0 = 0; k0 < C_; k0 += 16) {
        size_t aidx = (size_t)(row0 + arow) * C_ + k0 + ak;
        float4 c4 = *(const float4*)(g_ctx + aidx);
        float4 l4 = *(const float4*)(g_lepe + aidx);
        float4 bv4 = *(const float4*)(Wo + (size_t)(k0 + bkr) * C_ + col0 + bc);
        As[ak + 0][arow] = c4.x + l4.x;
        As[ak + 1][arow] = c4.y + l4.y;
        As[ak + 2][arow] = c4.z + l4.z;
        As[ak + 3][arow] = c4.w + l4.w;
        *(float4*)&Bs[bkr][bc] = bv4;
        __syncthreads();
#pragma unroll
        for (int kk = 0; kk < 16; kk++) {
            float4 a = *(const float4*)&As[kk][ty * 4];
            float4 b = *(const float4*)&Bs[kk][tx * 4];
            float aa[4] = {a.x, a.y, a.z, a.w};
            float bb[4] = {b.x, b.y, b.z, b.w};
#pragma unroll
            for (int i = 0; i < 4; i++)
#pragma unroll
                for (int j = 0; j < 4; j++)
                    acc[i][j] = fmaf(aa[i], bb[j], acc[i][j]);
        }
        __syncthreads();
    }

    const int gcol = col0 + tx * 4;
    float bias[4];
#pragma unroll
    for (int j = 0; j < 4; j++) bias[j] = bo[gcol + j];
#pragma unroll
    for (int i = 0; i < 4; i++) {
        int row = row0 + ty * 4 + i;
        *(float4*)&out[(size_t)row * C_ + gcol] =
            make_float4(acc[i][0] + bias[0], acc[i][1] + bias[1],
                        acc[i][2] + bias[2], acc[i][3] + bias[3]);
    }
}

// ---------------------------------------------------------------------------
extern "C" void kernel_launch(void* const* d_in, const int* in_sizes, int n_in,
                              void* d_out, int out_size)
{
    const float* x     = (const float*)d_in[0];
    const float* s_sin = (const float*)d_in[1];
    const float* s_cos = (const float*)d_in[2];
    const float* mask  = (const float*)d_in[3];
    const float* Wq    = (const float*)d_in[4];
    const float* bq    = (const float*)d_in[5];
    const float* Wk    = (const float*)d_in[6];
    const float* bk    = (const float*)d_in[7];
    const float* Wv    = (const float*)d_in[8];
    const float* bv    = (const float*)d_in[9];
    const float* dw_w  = (const float*)d_in[10];
    const float* dw_b  = (const float*)d_in[11];
    const float* Wo    = (const float*)d_in[12];
    const float* bo    = (const float*)d_in[13];
    float* out = (float*)d_out;

    cudaFuncSetAttribute(attn_kernel,
                         cudaFuncAttributeMaxDynamicSharedMemorySize,
                         ATTN_SMEM_BYTES);

    qkv_kernel<<<dim3(4, 144, 3), 256>>>(x, Wq, bq, Wk, bk, Wv, bv, s_sin, s_cos);
    lepe_kernel<<<ROWS_, 256>>>(dw_w, dw_b);
    attn_kernel<<<dim3(18, 32), 256, ATTN_SMEM_BYTES>>>(mask);
    out_kernel<<<dim3(4, 144), 256>>>(Wo, bo, out);
}

// round 13
// speedup vs baseline: 1.9303x; 1.9303x over previous
#include <cuda_runtime.h>
#include <cuda_bf16.h>
#include <stdint.h>
#include <math.h>

#define B_ 4
#define H_ 48
#define W_ 48
#define C_ 256
#define NH_ 8
#define D_ 32
#define N_ (H_*W_)          /* 2304 */
#define ROWS_ (B_*N_)       /* 9216 */
#define SCALE_ 0.17677669529663687f

// Scratch (device globals: no allocation allowed)
static __device__ float g_q[ROWS_*C_];
static __device__ float g_k[ROWS_*C_];
static __device__ float g_v[ROWS_*C_];
static __device__ float g_lepe[ROWS_*C_];
static __device__ float g_ctx[ROWS_*C_];

// ---------------------------------------------------------------------------
// Kernel 1: fused QKV GEMM (unchanged from passing baseline)
// ---------------------------------------------------------------------------
__global__ __launch_bounds__(256) void qkv_kernel(
    const float* __restrict__ x,
    const float* __restrict__ Wq, const float* __restrict__ bq,
    const float* __restrict__ Wk, const float* __restrict__ bk,
    const float* __restrict__ Wv, const float* __restrict__ bv,
    const float* __restrict__ s_sin, const float* __restrict__ s_cos)
{
    __shared__ float As[16][68];
    __shared__ float Bs[16][68];

    const int mat = blockIdx.z;
    const float* Wm = (mat == 0) ? Wq : (mat == 1) ? Wk : Wv;
    const float* bm = (mat == 0) ? bq : (mat == 1) ? bk : bv;

    const int tid = threadIdx.x;
    const int tx = tid & 15, ty = tid >> 4;
    const int row0 = blockIdx.y * 64;
    const int col0 = blockIdx.x * 64;

    const int arow = tid >> 2;
    const int ak   = (tid & 3) * 4;
    const int bkr  = tid >> 4;
    const int bc   = (tid & 15) * 4;

    float acc[4][4] = {};

    for (int k0 = 0; k0 < C_; k0 += 16) {
        float4 av = *(const float4*)(x + (size_t)(row0 + arow) * C_ + k0 + ak);
        float4 bv4 = *(const float4*)(Wm + (size_t)(k0 + bkr) * C_ + col0 + bc);
        As[ak + 0][arow] = av.x;
        As[ak + 1][arow] = av.y;
        As[ak + 2][arow] = av.z;
        As[ak + 3][arow] = av.w;
        *(float4*)&Bs[bkr][bc] = bv4;
        __syncthreads();
#pragma unroll
        for (int kk = 0; kk < 16; kk++) {
            float4 a = *(const float4*)&As[kk][ty * 4];
            float4 b = *(const float4*)&Bs[kk][tx * 4];
            float aa[4] = {a.x, a.y, a.z, a.w};
            float bb[4] = {b.x, b.y, b.z, b.w};
#pragma unroll
            for (int i = 0; i < 4; i++)
#pragma unroll
                for (int j = 0; j < 4; j++)
                    acc[i][j] = fmaf(aa[i], bb[j], acc[i][j]);
        }
        __syncthreads();
    }

    const int gcol = col0 + tx * 4;
    float bias[4];
#pragma unroll
    for (int j = 0; j < 4; j++) bias[j] = bm[gcol + j];

    float* dst = (mat == 0) ? g_q : (mat == 1) ? g_k : g_v;

#pragma unroll
    for (int i = 0; i < 4; i++) {
        int row = row0 + ty * 4 + i;
        int n = row % N_;
        float vals[4];
#pragma unroll
        for (int j = 0; j < 4; j++) {
            vals[j] = acc[i][j] + bias[j];
            if (mat == 1) vals[j] *= SCALE_;
        }
        if (mat < 2) {
#pragma unroll
            for (int p = 0; p < 4; p += 2) {
                int dd = (gcol + p) & (D_ - 1);
                float c0 = s_cos[n * D_ + dd];
                float s0 = s_sin[n * D_ + dd];
                float c1 = s_cos[n * D_ + dd + 1];
                float s1 = s_sin[n * D_ + dd + 1];
                float e = vals[p], o = vals[p + 1];
                vals[p]     = e * c0 - o * s0;
                vals[p + 1] = o * c1 + e * s1;
            }
        }
        *(float4*)&dst[(size_t)row * C_ + gcol] =
            make_float4(vals[0], vals[1], vals[2], vals[3]);
    }
}

// ---------------------------------------------------------------------------
// Kernel 2: depthwise 5x5 conv (LEPE) — unchanged
// ---------------------------------------------------------------------------
__global__ __launch_bounds__(256) void lepe_kernel(
    const float* __restrict__ dw_w, const float* __restrict__ dw_b)
{
    const int c = threadIdx.x;
    const int idx = blockIdx.x;
    const int xp = idx % W_;
    const int t = idx / W_;
    const int y = t % H_;
    const int b = t / H_;

    float acc = dw_b[c];
#pragma unroll
    for (int dy = 0; dy < 5; dy++) {
        int yy = y + dy - 2;
        if (yy < 0 || yy >= H_) continue;
#pragma unroll
        for (int dx = 0; dx < 5; dx++) {
            int xx = xp + dx - 2;
            if (xx < 0 || xx >= W_) continue;
            acc = fmaf(g_v[(size_t)((b * H_ + yy) * W_ + xx) * C_ + c],
                       dw_w[(dy * 5 + dx) * C_ + c], acc);
        }
    }
    g_lepe[(size_t)idx * C_ + c] = acc;
}

// ---------------------------------------------------------------------------
// Tensor-core helpers
// ---------------------------------------------------------------------------
__device__ __forceinline__ uint32_t packbf(float x0, float x1) {
    // returns bf16x2: x0 in low half, x1 in high half
    uint32_t r;
    asm("cvt.rn.bf16x2.f32 %0, %1, %2;" : "=r"(r) : "f"(x1), "f"(x0));
    return r;
}

__device__ __forceinline__ void split2(float x0, float x1,
                                       uint32_t& hi, uint32_t& lo) {
    hi = packbf(x0, x1);
    float h0 = __uint_as_float(hi << 16);
    float h1 = __uint_as_float(hi & 0xffff0000u);
    lo = packbf(x0 - h0, x1 - h1);
}

__device__ __forceinline__ void mma16816(float* d,
                                         uint32_t a0, uint32_t a1,
                                         uint32_t a2, uint32_t a3,
                                         uint32_t b0, uint32_t b1) {
    asm("mma.sync.aligned.m16n8k16.row.col.f32.bf16.bf16.f32 "
        "{%0,%1,%2,%3},{%4,%5,%6,%7},{%8,%9},{%0,%1,%2,%3};"
        : "+f"(d[0]), "+f"(d[1]), "+f"(d[2]), "+f"(d[3])
        : "r"(a0), "r"(a1), "r"(a2), "r"(a3), "r"(b0), "r"(b1));
}

// ---------------------------------------------------------------------------
// Kernel 3: flash attention, tensor-core bf16-split (3-product) version.
// Per CTA: one (b,h), 128 q-rows, 8 warps (16 rows each). KV tiles of 128.
// S fragments double as PV A-fragments (FA2 layout trick). Mask preloaded
// as the S accumulator init. 2-term bf16 split => fp32-grade accuracy.
// ---------------------------------------------------------------------------
__global__ __launch_bounds__(256) void attn_kernel(const float* __restrict__ mask)
{
    // K / Q staging: rows of 32 elems as 16 bf16x2 words, stride 20 words.
    __shared__ uint32_t kh[128 * 20];
    __shared__ uint32_t kl[128 * 20];
    // V transposed: vt[dd][kv] bf16, row stride 136 bf16 = 68 words.
    __shared__ uint32_t vth[32 * 68];
    __shared__ uint32_t vtl[32 * 68];

    const int tid  = threadIdx.x;
    const int warp = tid >> 5;
    const int lane = tid & 31;
    const int g    = lane >> 2;   // group row
    const int q    = lane & 3;    // quad id
    const int w16  = warp * 16;

    const int rb = blockIdx.x;            // 0..17
    const int bh = blockIdx.y;            // 0..31
    const int b = bh >> 3, h = bh & 7;
    const int row0 = rb * 128;

    // ---------------- Prologue: stage Q through kh/kl, grab fragments ------
    {
        const float* qb = g_q + ((size_t)b * N_ + row0) * C_ + h * D_;
#pragma unroll
        for (int i = 0; i < 4; i++) {
            int f = tid + i * 256;          // float4 index
            int r = f >> 3, d4 = f & 7;
            float4 t4 = *(const float4*)(qb + (size_t)r * C_ + d4 * 4);
            uint32_t h0, l0, h1, l1;
            split2(t4.x, t4.y, h0, l0);
            split2(t4.z, t4.w, h1, l1);
            kh[r * 20 + d4 * 2]     = h0;
            kh[r * 20 + d4 * 2 + 1] = h1;
            kl[r * 20 + d4 * 2]     = l0;
            kl[r * 20 + d4 * 2 + 1] = l1;
        }
    }
    __syncthreads();

    uint32_t qh[2][4], ql[2][4];
#pragma unroll
    for (int c = 0; c < 2; c++) {
        int base = (w16 + g) * 20 + 8 * c + q;
        qh[c][0] = kh[base];
        qh[c][1] = kh[base + 160];      // row +8
        qh[c][2] = kh[base + 4];        // k +8
        qh[c][3] = kh[base + 164];
        ql[c][0] = kl[base];
        ql[c][1] = kl[base + 160];
        ql[c][2] = kl[base + 4];
        ql[c][3] = kl[base + 164];
    }

    float m0 = -1e30f, m1 = -1e30f, l0s = 0.f, l1s = 0.f;
    float O[4][4] = {};

    const float* mrow = mask + (size_t)h * N_ * N_
                      + (size_t)(row0 + w16 + g) * N_ + 2 * q;

    for (int mt = 0; mt < N_; mt += 128) {
        __syncthreads();   // previous tile fully consumed (and Q frags read)

        // ---- load + convert K and V tiles -------------------------------
        {
            const float* kb = g_k + ((size_t)b * N_ + mt) * C_ + h * D_;
            const float* vb = g_v + ((size_t)b * N_ + mt) * C_ + h * D_;
            __nv_bfloat16* vhp = (__nv_bfloat16*)vth;
            __nv_bfloat16* vlp = (__nv_bfloat16*)vtl;
#pragma unroll
            for (int i = 0; i < 4; i++) {
                int f = tid + i * 256;
                int r = f >> 3, d4 = f & 7;
                float4 t4 = *(const float4*)(kb + (size_t)r * C_ + d4 * 4);
                uint32_t h0, lo0, h1, lo1;
                split2(t4.x, t4.y, h0, lo0);
                split2(t4.z, t4.w, h1, lo1);
                kh[r * 20 + d4 * 2]     = h0;
                kh[r * 20 + d4 * 2 + 1] = h1;
                kl[r * 20 + d4 * 2]     = lo0;
                kl[r * 20 + d4 * 2 + 1] = lo1;

                float4 v4 = *(const float4*)(vb + (size_t)r * C_ + d4 * 4);
                float vv[4] = {v4.x, v4.y, v4.z, v4.w};
#pragma unroll
                for (int e = 0; e < 4; e++) {
                    int dd = d4 * 4 + e;
                    __nv_bfloat16 bhv = __float2bfloat16(vv[e]);
                    vhp[dd * 136 + r] = bhv;
                    vlp[dd * 136 + r] =
                        __float2bfloat16(vv[e] - __bfloat162float(bhv));
                }
            }
        }
        __syncthreads();

        // ---- S init = mask fragments ------------------------------------
        float s[16][4];
        const float* mb = mrow + mt;
#pragma unroll
        for (int j = 0; j < 16; j++) {
            float2 a = *(const float2*)(mb + j * 8);
            float2 c = *(const float2*)(mb + (size_t)8 * N_ + j * 8);
            s[j][0] = a.x; s[j][1] = a.y; s[j][2] = c.x; s[j][3] = c.y;
        }

        // ---- GEMM1: S += Q K^T (3-product bf16 split) -------------------
#pragma unroll
        for (int c = 0; c < 2; c++) {
#pragma unroll
            for (int j = 0; j < 16; j++) {
                int bb = (j * 8 + g) * 20 + 8 * c + q;
                uint32_t bh0 = kh[bb], bh1 = kh[bb + 4];
                uint32_t bl0 = kl[bb], bl1 = kl[bb + 4];
                mma16816(s[j], qh[c][0], qh[c][1], qh[c][2], qh[c][3], bh0, bh1);
                mma16816(s[j], qh[c][0], qh[c][1], qh[c][2], qh[c][3], bl0, bl1);
                mma16816(s[j], ql[c][0], ql[c][1], ql[c][2], ql[c][3], bh0, bh1);
            }
        }

        // ---- online softmax in fragments --------------------------------
        float mx0 = -1e30f, mx1 = -1e30f;
#pragma unroll
        for (int j = 0; j < 16; j++) {
            mx0 = fmaxf(mx0, fmaxf(s[j][0], s[j][1]));
            mx1 = fmaxf(mx1, fmaxf(s[j][2], s[j][3]));
        }
        mx0 = fmaxf(mx0, __shfl_xor_sync(0xffffffffu, mx0, 1, 4));
        mx0 = fmaxf(mx0, __shfl_xor_sync(0xffffffffu, mx0, 2, 4));
        mx1 = fmaxf(mx1, __shfl_xor_sync(0xffffffffu, mx1, 1, 4));
        mx1 = fmaxf(mx1, __shfl_xor_sync(0xffffffffu, mx1, 2, 4));

        float nm0 = fmaxf(m0, mx0), nm1 = fmaxf(m1, mx1);
        float cr0 = __expf(m0 - nm0), cr1 = __expf(m1 - nm1);
        m0 = nm0; m1 = nm1;

        float rs0 = 0.f, rs1 = 0.f;
#pragma unroll
        for (int j = 0; j < 16; j++) {
            s[j][0] = __expf(s[j][0] - nm0); rs0 += s[j][0];
            s[j][1] = __expf(s[j][1] - nm0); rs0 += s[j][1];
            s[j][2] = __expf(s[j][2] - nm1); rs1 += s[j][2];
            s[j][3] = __expf(s[j][3] - nm1); rs1 += s[j][3];
        }
        rs0 += __shfl_xor_sync(0xffffffffu, rs0, 1, 4);
        rs0 += __shfl_xor_sync(0xffffffffu, rs0, 2, 4);
        rs1 += __shfl_xor_sync(0xffffffffu, rs1, 1, 4);
        rs1 += __shfl_xor_sync(0xffffffffu, rs1, 2, 4);
        l0s = l0s * cr0 + rs0;
        l1s = l1s * cr1 + rs1;
#pragma unroll
        for (int n = 0; n < 4; n++) {
            O[n][0] *= cr0; O[n][1] *= cr0;
            O[n][2] *= cr1; O[n][3] *= cr1;
        }

        // ---- GEMM2: O += P V (P fragments reused as A-fragments) --------
#pragma unroll
        for (int t = 0; t < 8; t++) {
            uint32_t ah[4], al[4];
            split2(s[2 * t][0],     s[2 * t][1],     ah[0], al[0]);
            split2(s[2 * t][2],     s[2 * t][3],     ah[1], al[1]);
            split2(s[2 * t + 1][0], s[2 * t + 1][1], ah[2], al[2]);
            split2(s[2 * t + 1][2], s[2 * t + 1][3], ah[3], al[3]);
#pragma unroll
            for (int n = 0; n < 4; n++) {
                int vb = (n * 8 + g) * 68 + 8 * t + q;
                uint32_t bh0 = vth[vb], bh1 = vth[vb + 4];
                uint32_t bl0 = vtl[vb], bl1 = vtl[vb + 4];
                mma16816(O[n], ah[0], ah[1], ah[2], ah[3], bh0, bh1);
                mma16816(O[n], ah[0], ah[1], ah[2], ah[3], bl0, bl1);
                mma16816(O[n], al[0], al[1], al[2], al[3], bh0, bh1);
            }
        }
    }

    // ---- epilogue: normalize, write ctx ---------------------------------
    float inv0 = 1.f / l0s, inv1 = 1.f / l1s;
    int r0 = row0 + w16 + g;
    float* cb0 = g_ctx + ((size_t)b * N_ + r0) * C_ + h * D_ + 2 * q;
    float* cb1 = cb0 + (size_t)8 * C_;
#pragma unroll
    for (int n = 0; n < 4; n++) {
        *(float2*)(cb0 + n * 8) = make_float2(O[n][0] * inv0, O[n][1] * inv0);
        *(float2*)(cb1 + n * 8) = make_float2(O[n][2] * inv1, O[n][3] * inv1);
    }
}

// ---------------------------------------------------------------------------
// Kernel 4: out = (ctx + lepe) @ Wo + bo — unchanged
// ---------------------------------------------------------------------------
__global__ __launch_bounds__(256) void out_kernel(
    const float* __restrict__ Wo, const float* __restrict__ bo,
    float* __restrict__ out)
{
    __shared__ float As[16][68];
    __shared__ float Bs[16][68];

    const int tid = threadIdx.x;
    const int tx = tid & 15, ty = tid >> 4;
    const int row0 = blockIdx.y * 64;
    const int col0 = blockIdx.x * 64;

    const int arow = tid >> 2;
    const int ak   = (tid & 3) * 4;
    const int bkr  = tid >> 4;
    const int bc   = (tid & 15) * 4;

    float acc[4][4] = {};

    for (int k0 = 0; k0 < C_; k0 += 16) {
        size_t aidx = (size_t)(row0 + arow) * C_ + k0 + ak;
        float4 c4 = *(const float4*)(g_ctx + aidx);
        float4 l4 = *(const float4*)(g_lepe + aidx);
        float4 bv4 = *(const float4*)(Wo + (size_t)(k0 + bkr) * C_ + col0 + bc);
        As[ak + 0][arow] = c4.x + l4.x;
        As[ak + 1][arow] = c4.y + l4.y;
        As[ak + 2][arow] = c4.z + l4.z;
        As[ak + 3][arow] = c4.w + l4.w;
        *(float4*)&Bs[bkr][bc] = bv4;
        __syncthreads();
#pragma unroll
        for (int kk = 0; kk < 16; kk++) {
            float4 a = *(const float4*)&As[kk][ty * 4];
            float4 b = *(const float4*)&Bs[kk][tx * 4];
            float aa[4] = {a.x, a.y, a.z, a.w};
            float bb[4] = {b.x, b.y, b.z, b.w};
#pragma unroll
            for (int i = 0; i < 4; i++)
#pragma unroll
                for (int j = 0; j < 4; j++)
                    acc[i][j] = fmaf(aa[i], bb[j], acc[i][j]);
        }
        __syncthreads();
    }

    const int gcol = col0 + tx * 4;
    float bias[4];
#pragma unroll
    for (int j = 0; j < 4; j++) bias[j] = bo[gcol + j];
#pragma unroll
    for (int i = 0; i < 4; i++) {
        int row = row0 + ty * 4 + i;
        *(float4*)&out[(size_t)row * C_ + gcol] =
            make_float4(acc[i][0] + bias[0], acc[i][1] + bias[1],
                        acc[i][2] + bias[2], acc[i][3] + bias[3]);
    }
}

// ---------------------------------------------------------------------------
extern "C" void kernel_launch(void* const* d_in, const int* in_sizes, int n_in,
                              void* d_out, int out_size)
{
    const float* x     = (const float*)d_in[0];
    const float* s_sin = (const float*)d_in[1];
    const float* s_cos = (const float*)d_in[2];
    const float* mask  = (const float*)d_in[3];
    const float* Wq    = (const float*)d_in[4];
    const float* bq    = (const float*)d_in[5];
    const float* Wk    = (const float*)d_in[6];
    const float* bk    = (const float*)d_in[7];
    const float* Wv    = (const float*)d_in[8];
    const float* bv    = (const float*)d_in[9];
    const float* dw_w  = (const float*)d_in[10];
    const float* dw_b  = (const float*)d_in[11];
    const float* Wo    = (const float*)d_in[12];
    const float* bo    = (const float*)d_in[13];
    float* out = (float*)d_out;

    qkv_kernel<<<dim3(4, 144, 3), 256>>>(x, Wq, bq, Wk, bk, Wv, bv, s_sin, s_cos);
    lepe_kernel<<<ROWS_, 256>>>(dw_w, dw_b);
    attn_kernel<<<dim3(18, 32), 256>>>(mask);
    out_kernel<<<dim3(4, 144), 256>>>(Wo, bo, out);
}

// round 14
// speedup vs baseline: 1.9538x; 1.0122x over previous
#include <cuda_runtime.h>
#include <cuda_bf16.h>
#include <stdint.h>
#include <math.h>

#define B_ 4
#define H_ 48
#define W_ 48
#define C_ 256
#define NH_ 8
#define D_ 32
#define N_ (H_*W_)          /* 2304 */
#define ROWS_ (B_*N_)       /* 9216 */
#define SCALE_ 0.17677669529663687f

// Scratch (device globals: no allocation allowed)
static __device__ float g_q[ROWS_*C_];
static __device__ float g_k[ROWS_*C_];
static __device__ float g_v[ROWS_*C_];
static __device__ float g_lepe[ROWS_*C_];
static __device__ float g_ctx[ROWS_*C_];

// ---------------------------------------------------------------------------
// Tensor-core helpers (verified in R13)
// ---------------------------------------------------------------------------
__device__ __forceinline__ uint32_t packbf(float x0, float x1) {
    uint32_t r;
    asm("cvt.rn.bf16x2.f32 %0, %1, %2;" : "=r"(r) : "f"(x1), "f"(x0));
    return r;
}

__device__ __forceinline__ void split2(float x0, float x1,
                                       uint32_t& hi, uint32_t& lo) {
    hi = packbf(x0, x1);
    float h0 = __uint_as_float(hi << 16);
    float h1 = __uint_as_float(hi & 0xffff0000u);
    lo = packbf(x0 - h0, x1 - h1);
}

__device__ __forceinline__ void mma16816(float* d,
                                         uint32_t a0, uint32_t a1,
                                         uint32_t a2, uint32_t a3,
                                         uint32_t b0, uint32_t b1) {
    asm("mma.sync.aligned.m16n8k16.row.col.f32.bf16.bf16.f32 "
        "{%0,%1,%2,%3},{%4,%5,%6,%7},{%8,%9},{%0,%1,%2,%3};"
        : "+f"(d[0]), "+f"(d[1]), "+f"(d[2]), "+f"(d[3])
        : "r"(a0), "r"(a1), "r"(a2), "r"(a3), "r"(b0), "r"(b1));
}

// ---------------------------------------------------------------------------
// Kernel 1: QKV GEMM on tensor cores. CTA tile 64 rows x 64 cols, K-chunks
// of 64. x staged k-major (attn-K pattern); W transpose-staged (attn-V
// pattern). 3-product bf16 split. Epilogue: bias (+scale K), RoPE for Q/K.
// Warps: wr = warp&3 (16 rows), wc = warp>>2 (32 cols).
// ---------------------------------------------------------------------------
__global__ __launch_bounds__(256) void qkv_mma_kernel(
    const float* __restrict__ x,
    const float* __restrict__ Wq, const float* __restrict__ bq,
    const float* __restrict__ Wk, const float* __restrict__ bk,
    const float* __restrict__ Wv, const float* __restrict__ bv,
    const float* __restrict__ s_sin, const float* __restrict__ s_cos)
{
    __shared__ uint32_t xh[64 * 36], xl[64 * 36];
    __shared__ uint32_t wh[64 * 36], wl[64 * 36];

    const int mat = blockIdx.z;
    const float* Wm = (mat == 0) ? Wq : (mat == 1) ? Wk : Wv;
    const float* bm = (mat == 0) ? bq : (mat == 1) ? bk : bv;

    const int tid  = threadIdx.x;
    const int warp = tid >> 5, lane = tid & 31;
    const int g = lane >> 2, q = lane & 3;
    const int wr = warp & 3, wc = warp >> 2;
    const int row0 = blockIdx.y * 64;
    const int col0 = blockIdx.x * 64;

    float s[4][4] = {};

    for (int k0 = 0; k0 < C_; k0 += 64) {
        __syncthreads();
        __nv_bfloat16* whp = (__nv_bfloat16*)wh;
        __nv_bfloat16* wlp = (__nv_bfloat16*)wl;
#pragma unroll
        for (int i = 0; i < 4; i++) {
            int e = tid + i * 256;
            // x: row r, k-offset d4*4 (k-major staging, attn-K pattern)
            int r = e >> 4, d4 = e & 15;
            float4 t4 = *(const float4*)(x + (size_t)(row0 + r) * C_ + k0 + d4 * 4);
            uint32_t h0, l0, h1, l1;
            split2(t4.x, t4.y, h0, l0);
            split2(t4.z, t4.w, h1, l1);
            xh[r * 36 + d4 * 2]     = h0;
            xh[r * 36 + d4 * 2 + 1] = h1;
            xl[r * 36 + d4 * 2]     = l0;
            xl[r * 36 + d4 * 2 + 1] = l1;
            // W: k-row kk, 4 cols; transpose-scatter (attn-V pattern)
            int kk = e >> 4, c4 = e & 15;
            float4 w4 = *(const float4*)(Wm + (size_t)(k0 + kk) * C_ + col0 + c4 * 4);
            float wv[4] = {w4.x, w4.y, w4.z, w4.w};
#pragma unroll
            for (int sx = 0; sx < 4; sx++) {
                __nv_bfloat16 hv = __float2bfloat16(wv[sx]);
                whp[(c4 * 4 + sx) * 72 + kk] = hv;
                wlp[(c4 * 4 + sx) * 72 + kk] =
                    __float2bfloat16(wv[sx] - __bfloat162float(hv));
            }
        }
        __syncthreads();

#pragma unroll
        for (int c = 0; c < 4; c++) {
            int ab = (wr * 16 + g) * 36 + 8 * c + q;
            uint32_t ah0 = xh[ab], ah1 = xh[ab + 288];
            uint32_t ah2 = xh[ab + 4], ah3 = xh[ab + 292];
            uint32_t al0 = xl[ab], al1 = xl[ab + 288];
            uint32_t al2 = xl[ab + 4], al3 = xl[ab + 292];
#pragma unroll
            for (int j = 0; j < 4; j++) {
                int bb = (wc * 32 + j * 8 + g) * 36 + 8 * c + q;
                uint32_t bh0 = wh[bb], bh1 = wh[bb + 4];
                uint32_t bl0 = wl[bb], bl1 = wl[bb + 4];
                mma16816(s[j], ah0, ah1, ah2, ah3, bh0, bh1);
                mma16816(s[j], ah0, ah1, ah2, ah3, bl0, bl1);
                mma16816(s[j], al0, al1, al2, al3, bh0, bh1);
            }
        }
    }

    // epilogue
    float* dst = (mat == 0) ? g_q : (mat == 1) ? g_k : g_v;
    int r0g = row0 + wr * 16 + g;
#pragma unroll
    for (int j = 0; j < 4; j++) {
        int gc = col0 + wc * 32 + j * 8 + 2 * q;
        float b0v = bm[gc], b1v = bm[gc + 1];
#pragma unroll
        for (int half = 0; half < 2; half++) {
            int row = r0g + half * 8;
            float v0 = s[j][half * 2 + 0] + b0v;
            float v1 = s[j][half * 2 + 1] + b1v;
            if (mat == 1) { v0 *= SCALE_; v1 *= SCALE_; }
            if (mat < 2) {
                int n = row % N_;
                int dd = gc & (D_ - 1);
                float c0 = s_cos[n * D_ + dd],     s0v = s_sin[n * D_ + dd];
                float c1 = s_cos[n * D_ + dd + 1], s1v = s_sin[n * D_ + dd + 1];
                float e = v0, o = v1;
                v0 = e * c0 - o * s0v;
                v1 = o * c1 + e * s1v;
            }
            *(float2*)&dst[(size_t)row * C_ + gc] = make_float2(v0, v1);
        }
    }
}

// ---------------------------------------------------------------------------
// Kernel 2: depthwise 5x5 conv (LEPE) — unchanged
// ---------------------------------------------------------------------------
__global__ __launch_bounds__(256) void lepe_kernel(
    const float* __restrict__ dw_w, const float* __restrict__ dw_b)
{
    const int c = threadIdx.x;
    const int idx = blockIdx.x;
    const int xp = idx % W_;
    const int t = idx / W_;
    const int y = t % H_;
    const int b = t / H_;

    float acc = dw_b[c];
#pragma unroll
    for (int dy = 0; dy < 5; dy++) {
        int yy = y + dy - 2;
        if (yy < 0 || yy >= H_) continue;
#pragma unroll
        for (int dx = 0; dx < 5; dx++) {
            int xx = xp + dx - 2;
            if (xx < 0 || xx >= W_) continue;
            acc = fmaf(g_v[(size_t)((b * H_ + yy) * W_ + xx) * C_ + c],
                       dw_w[(dy * 5 + dx) * C_ + c], acc);
        }
    }
    g_lepe[(size_t)idx * C_ + c] = acc;
}

// ---------------------------------------------------------------------------
// Kernel 3: flash attention (verified R13) — unchanged
// ---------------------------------------------------------------------------
__global__ __launch_bounds__(256) void attn_kernel(const float* __restrict__ mask)
{
    __shared__ uint32_t kh[128 * 20];
    __shared__ uint32_t kl[128 * 20];
    __shared__ uint32_t vth[32 * 68];
    __shared__ uint32_t vtl[32 * 68];

    const int tid  = threadIdx.x;
    const int warp = tid >> 5;
    const int lane = tid & 31;
    const int g    = lane >> 2;
    const int q    = lane & 3;
    const int w16  = warp * 16;

    const int rb = blockIdx.x;
    const int bh = blockIdx.y;
    const int b = bh >> 3, h = bh & 7;
    const int row0 = rb * 128;

    {
        const float* qb = g_q + ((size_t)b * N_ + row0) * C_ + h * D_;
#pragma unroll
        for (int i = 0; i < 4; i++) {
            int f = tid + i * 256;
            int r = f >> 3, d4 = f & 7;
            float4 t4 = *(const float4*)(qb + (size_t)r * C_ + d4 * 4);
            uint32_t h0, l0, h1, l1;
            split2(t4.x, t4.y, h0, l0);
            split2(t4.z, t4.w, h1, l1);
            kh[r * 20 + d4 * 2]     = h0;
            kh[r * 20 + d4 * 2 + 1] = h1;
            kl[r * 20 + d4 * 2]     = l0;
            kl[r * 20 + d4 * 2 + 1] = l1;
        }
    }
    __syncthreads();

    uint32_t qh[2][4], ql[2][4];
#pragma unroll
    for (int c = 0; c < 2; c++) {
        int base = (w16 + g) * 20 + 8 * c + q;
        qh[c][0] = kh[base];
        qh[c][1] = kh[base + 160];
        qh[c][2] = kh[base + 4];
        qh[c][3] = kh[base + 164];
        ql[c][0] = kl[base];
        ql[c][1] = kl[base + 160];
        ql[c][2] = kl[base + 4];
        ql[c][3] = kl[base + 164];
    }

    float m0 = -1e30f, m1 = -1e30f, l0s = 0.f, l1s = 0.f;
    float O[4][4] = {};

    const float* mrow = mask + (size_t)h * N_ * N_
                      + (size_t)(row0 + w16 + g) * N_ + 2 * q;

    for (int mt = 0; mt < N_; mt += 128) {
        __syncthreads();

        {
            const float* kb = g_k + ((size_t)b * N_ + mt) * C_ + h * D_;
            const float* vb = g_v + ((size_t)b * N_ + mt) * C_ + h * D_;
            __nv_bfloat16* vhp = (__nv_bfloat16*)vth;
            __nv_bfloat16* vlp = (__nv_bfloat16*)vtl;
#pragma unroll
            for (int i = 0; i < 4; i++) {
                int f = tid + i * 256;
                int r = f >> 3, d4 = f & 7;
                float4 t4 = *(const float4*)(kb + (size_t)r * C_ + d4 * 4);
                uint32_t h0, lo0, h1, lo1;
                split2(t4.x, t4.y, h0, lo0);
                split2(t4.z, t4.w, h1, lo1);
                kh[r * 20 + d4 * 2]     = h0;
                kh[r * 20 + d4 * 2 + 1] = h1;
                kl[r * 20 + d4 * 2]     = lo0;
                kl[r * 20 + d4 * 2 + 1] = lo1;

                float4 v4 = *(const float4*)(vb + (size_t)r * C_ + d4 * 4);
                float vv[4] = {v4.x, v4.y, v4.z, v4.w};
#pragma unroll
                for (int e = 0; e < 4; e++) {
                    int dd = d4 * 4 + e;
                    __nv_bfloat16 bhv = __float2bfloat16(vv[e]);
                    vhp[dd * 136 + r] = bhv;
                    vlp[dd * 136 + r] =
                        __float2bfloat16(vv[e] - __bfloat162float(bhv));
                }
            }
        }
        __syncthreads();

        float s[16][4];
        const float* mb = mrow + mt;
#pragma unroll
        for (int j = 0; j < 16; j++) {
            float2 a = *(const float2*)(mb + j * 8);
            float2 c = *(const float2*)(mb + (size_t)8 * N_ + j * 8);
            s[j][0] = a.x; s[j][1] = a.y; s[j][2] = c.x; s[j][3] = c.y;
        }

#pragma unroll
        for (int c = 0; c < 2; c++) {
#pragma unroll
            for (int j = 0; j < 16; j++) {
                int bb = (j * 8 + g) * 20 + 8 * c + q;
                uint32_t bh0 = kh[bb], bh1 = kh[bb + 4];
                uint32_t bl0 = kl[bb], bl1 = kl[bb + 4];
                mma16816(s[j], qh[c][0], qh[c][1], qh[c][2], qh[c][3], bh0, bh1);
                mma16816(s[j], qh[c][0], qh[c][1], qh[c][2], qh[c][3], bl0, bl1);
                mma16816(s[j], ql[c][0], ql[c][1], ql[c][2], ql[c][3], bh0, bh1);
            }
        }

        float mx0 = -1e30f, mx1 = -1e30f;
#pragma unroll
        for (int j = 0; j < 16; j++) {
            mx0 = fmaxf(mx0, fmaxf(s[j][0], s[j][1]));
            mx1 = fmaxf(mx1, fmaxf(s[j][2], s[j][3]));
        }
        mx0 = fmaxf(mx0, __shfl_xor_sync(0xffffffffu, mx0, 1, 4));
        mx0 = fmaxf(mx0, __shfl_xor_sync(0xffffffffu, mx0, 2, 4));
        mx1 = fmaxf(mx1, __shfl_xor_sync(0xffffffffu, mx1, 1, 4));
        mx1 = fmaxf(mx1, __shfl_xor_sync(0xffffffffu, mx1, 2, 4));

        float nm0 = fmaxf(m0, mx0), nm1 = fmaxf(m1, mx1);
        float cr0 = __expf(m0 - nm0), cr1 = __expf(m1 - nm1);
        m0 = nm0; m1 = nm1;

        float rs0 = 0.f, rs1 = 0.f;
#pragma unroll
        for (int j = 0; j < 16; j++) {
            s[j][0] = __expf(s[j][0] - nm0); rs0 += s[j][0];
            s[j][1] = __expf(s[j][1] - nm0); rs0 += s[j][1];
            s[j][2] = __expf(s[j][2] - nm1); rs1 += s[j][2];
            s[j][3] = __expf(s[j][3] - nm1); rs1 += s[j][3];
        }
        rs0 += __shfl_xor_sync(0xffffffffu, rs0, 1, 4);
        rs0 += __shfl_xor_sync(0xffffffffu, rs0, 2, 4);
        rs1 += __shfl_xor_sync(0xffffffffu, rs1, 1, 4);
        rs1 += __shfl_xor_sync(0xffffffffu, rs1, 2, 4);
        l0s = l0s * cr0 + rs0;
        l1s = l1s * cr1 + rs1;
#pragma unroll
        for (int n = 0; n < 4; n++) {
            O[n][0] *= cr0; O[n][1] *= cr0;
            O[n][2] *= cr1; O[n][3] *= cr1;
        }

#pragma unroll
        for (int t = 0; t < 8; t++) {
            uint32_t ah[4], al[4];
            split2(s[2 * t][0],     s[2 * t][1],     ah[0], al[0]);
            split2(s[2 * t][2],     s[2 * t][3],     ah[1], al[1]);
            split2(s[2 * t + 1][0], s[2 * t + 1][1], ah[2], al[2]);
            split2(s[2 * t + 1][2], s[2 * t + 1][3], ah[3], al[3]);
#pragma unroll
            for (int n = 0; n < 4; n++) {
                int vb = (n * 8 + g) * 68 + 8 * t + q;
                uint32_t bh0 = vth[vb], bh1 = vth[vb + 4];
                uint32_t bl0 = vtl[vb], bl1 = vtl[vb + 4];
                mma16816(O[n], ah[0], ah[1], ah[2], ah[3], bh0, bh1);
                mma16816(O[n], ah[0], ah[1], ah[2], ah[3], bl0, bl1);
                mma16816(O[n], al[0], al[1], al[2], al[3], bh0, bh1);
            }
        }
    }

    float inv0 = 1.f / l0s, inv1 = 1.f / l1s;
    int r0 = row0 + w16 + g;
    float* cb0 = g_ctx + ((size_t)b * N_ + r0) * C_ + h * D_ + 2 * q;
    float* cb1 = cb0 + (size_t)8 * C_;
#pragma unroll
    for (int n = 0; n < 4; n++) {
        *(float2*)(cb0 + n * 8) = make_float2(O[n][0] * inv0, O[n][1] * inv0);
        *(float2*)(cb1 + n * 8) = make_float2(O[n][2] * inv1, O[n][3] * inv1);
    }
}

// ---------------------------------------------------------------------------
// Kernel 4: out = (ctx + lepe) @ Wo + bo on tensor cores (same structure as
// qkv_mma; lepe fused into the A-stage).
// ---------------------------------------------------------------------------
__global__ __launch_bounds__(256) void out_mma_kernel(
    const float* __restrict__ Wo, const float* __restrict__ bo,
    float* __restrict__ out)
{
    __shared__ uint32_t xh[64 * 36], xl[64 * 36];
    __shared__ uint32_t wh[64 * 36], wl[64 * 36];

    const int tid  = threadIdx.x;
    const int warp = tid >> 5, lane = tid & 31;
    const int g = lane >> 2, q = lane & 3;
    const int wr = warp & 3, wc = warp >> 2;
    const int row0 = blockIdx.y * 64;
    const int col0 = blockIdx.x * 64;

    float s[4][4] = {};

    for (int k0 = 0; k0 < C_; k0 += 64) {
        __syncthreads();
        __nv_bfloat16* whp = (__nv_bfloat16*)wh;
        __nv_bfloat16* wlp = (__nv_bfloat16*)wl;
#pragma unroll
        for (int i = 0; i < 4; i++) {
            int e = tid + i * 256;
            int r = e >> 4, d4 = e & 15;
            size_t aidx = (size_t)(row0 + r) * C_ + k0 + d4 * 4;
            float4 c4v = *(const float4*)(g_ctx + aidx);
            float4 l4v = *(const float4*)(g_lepe + aidx);
            uint32_t h0, l0, h1, l1;
            split2(c4v.x + l4v.x, c4v.y + l4v.y, h0, l0);
            split2(c4v.z + l4v.z, c4v.w + l4v.w, h1, l1);
            xh[r * 36 + d4 * 2]     = h0;
            xh[r * 36 + d4 * 2 + 1] = h1;
            xl[r * 36 + d4 * 2]     = l0;
            xl[r * 36 + d4 * 2 + 1] = l1;

            int kk = e >> 4, c4 = e & 15;
            float4 w4 = *(const float4*)(Wo + (size_t)(k0 + kk) * C_ + col0 + c4 * 4);
            float wv[4] = {w4.x, w4.y, w4.z, w4.w};
#pragma unroll
            for (int sx = 0; sx < 4; sx++) {
                __nv_bfloat16 hv = __float2bfloat16(wv[sx]);
                whp[(c4 * 4 + sx) * 72 + kk] = hv;
                wlp[(c4 * 4 + sx) * 72 + kk] =
                    __float2bfloat16(wv[sx] - __bfloat162float(hv));
            }
        }
        __syncthreads();

#pragma unroll
        for (int c = 0; c < 4; c++) {
            int ab = (wr * 16 + g) * 36 + 8 * c + q;
            uint32_t ah0 = xh[ab], ah1 = xh[ab + 288];
            uint32_t ah2 = xh[ab + 4], ah3 = xh[ab + 292];
            uint32_t al0 = xl[ab], al1 = xl[ab + 288];
            uint32_t al2 = xl[ab + 4], al3 = xl[ab + 292];
#pragma unroll
            for (int j = 0; j < 4; j++) {
                int bb = (wc * 32 + j * 8 + g) * 36 + 8 * c + q;
                uint32_t bh0 = wh[bb], bh1 = wh[bb + 4];
                uint32_t bl0 = wl[bb], bl1 = wl[bb + 4];
                mma16816(s[j], ah0, ah1, ah2, ah3, bh0, bh1);
                mma16816(s[j], ah0, ah1, ah2, ah3, bl0, bl1);
                mma16816(s[j], al0, al1, al2, al3, bh0, bh1);
            }
        }
    }

    int r0g = row0 + wr * 16 + g;
#pragma unroll
    for (int j = 0; j < 4; j++) {
        int gc = col0 + wc * 32 + j * 8 + 2 * q;
        float b0v = bo[gc], b1v = bo[gc + 1];
        *(float2*)&out[(size_t)r0g * C_ + gc] =
            make_float2(s[j][0] + b0v, s[j][1] + b1v);
        *(float2*)&out[(size_t)(r0g + 8) * C_ + gc] =
            make_float2(s[j][2] + b0v, s[j][3] + b1v);
    }
}

// ---------------------------------------------------------------------------
extern "C" void kernel_launch(void* const* d_in, const int* in_sizes, int n_in,
                              void* d_out, int out_size)
{
    const float* x     = (const float*)d_in[0];
    const float* s_sin = (const float*)d_in[1];
    const float* s_cos = (const float*)d_in[2];
    const float* mask  = (const float*)d_in[3];
    const float* Wq    = (const float*)d_in[4];
    const float* bq    = (const float*)d_in[5];
    const float* Wk    = (const float*)d_in[6];
    const float* bk    = (const float*)d_in[7];
    const float* Wv    = (const float*)d_in[8];
    const float* bv    = (const float*)d_in[9];
    const float* dw_w  = (const float*)d_in[10];
    const float* dw_b  = (const float*)d_in[11];
    const float* Wo    = (const float*)d_in[12];
    const float* bo    = (const float*)d_in[13];
    float* out = (float*)d_out;

    qkv_mma_kernel<<<dim3(4, 144, 3), 256>>>(x, Wq, bq, Wk, bk, Wv, bv, s_sin, s_cos);
    lepe_kernel<<<ROWS_, 256>>>(dw_w, dw_b);
    attn_kernel<<<dim3(18, 32), 256>>>(mask);
    out_mma_kernel<<<dim3(4, 144), 256>>>(Wo, bo, out);
}